// round 1
// baseline (speedup 1.0000x reference)
#include <cuda_runtime.h>
#include <math.h>

// ---------------------------------------------------------------------------
// Self-Organizing Map, faithful sequential scan, as ONE persistent kernel.
//
//   grid 32x32 = 1024 cells, dim 384, 8192 samples, lr=0.1, sigma=1.
//   step t: d2_j = ||x_t - w_j||^2 ; bmu = argmin_j d2_j (first index on tie)
//           a_j  = 0.1 * exp(-0.5 * sqrt(dx^2+dy^2))   (grid distance, NOT squared)
//           w_j += a_j * (x_t - w_j)                    (ALL cells updated)
//
// Critical-path trick: with u = x_{t+1}-w, v = x_t-w (pre-BMU computable),
//   d2_{t+1} = P - 2 a Q + a^2 R,  P=||u||^2, Q=<u,v>, R=||v||^2 (= d2_t).
// So once BMU_t arrives, next step's distances are 2 FMAs per cell; the
// vector pass (weight update + next P/Q/R) hides under the inter-CTA sync.
//
// Layout: 128 CTAs x 256 threads. One warp per cell (8 cells/CTA),
// 12 weight elems per lane (dims lane+32k), weights live in registers.
// Per-step communication: each CTA STGs one packed (d2_bits<<32 | cell)
// min into g_slots[s*128 + cta]; every CTA's warp0 polls the 128 slots
// (volatile, L1-bypass) and shuffle-reduces the global min.
// ---------------------------------------------------------------------------

#define SOM_G      128          // CTAs (1 per SM, single wave on 148 SMs)
#define SOM_TPB    256
#define SOM_DIM    384
#define SOM_NS     8192
#define SOM_EPW    12           // DIM / 32
#define SOM_MAXE   2            // epoch capacity (dataset uses 1)
#define SOM_MAXSTEPS (SOM_MAXE * SOM_NS)
#define INVSLOT 0xFFFFFFFFFFFFFFFFULL

// per-(step,cta) packed mins; valid entries never equal the sentinel
// (high 32 bits are finite-nonneg float bits <= 0x7F7FFFFF).
__device__ unsigned long long g_slots[(size_t)(SOM_MAXSTEPS + 1) * SOM_G];

__device__ __forceinline__ unsigned long long umin64(unsigned long long a,
                                                     unsigned long long b) {
    return a < b ? a : b;
}

__device__ __forceinline__ int read_epochs(const int* p) {
    int e = p[0];
    if (e < 1 || e > SOM_MAXE) {
        // defensive: tolerate the scalar arriving as a float bit pattern
        float fe = __int_as_float(e);
        if (fe >= 1.0f && fe <= (float)SOM_MAXE) e = (int)fe;
        else e = 1;
    }
    return e;
}

__global__ void som_init_slots(const int* __restrict__ pep) {
    const int S = read_epochs(pep) * SOM_NS;
    const size_t total = (size_t)(S + 1) * SOM_G;
    for (size_t i = (size_t)blockIdx.x * blockDim.x + threadIdx.x; i < total;
         i += (size_t)gridDim.x * blockDim.x)
        g_slots[i] = INVSLOT;
}

__global__ void __launch_bounds__(SOM_TPB, 1)
som_kernel(const float* __restrict__ X,   // [8192, 384]
           const float* __restrict__ W0,  // [32, 32, 384]
           const int* __restrict__ pep,   // num_epochs
           float* __restrict__ out)       // [32, 32, 384]
{
    __shared__ float lut[63 * 64];               // a(dx,dy), dx,dy in [-31,31]
    __shared__ unsigned long long s_cellmin[8];  // per-warp (cell) packed d2
    __shared__ unsigned long long s_bmu;         // broadcast of global min

    const int tid  = threadIdx.x;
    const int wid  = tid >> 5;
    const int lane = tid & 31;
    const int cta  = blockIdx.x;
    const int cell = (cta << 3) + wid;           // 0..1023, flat = gx*32+gy
    const int cgx  = cell >> 5;
    const int cgy  = cell & 31;
    const int S    = read_epochs(pep) * SOM_NS;

    // neighborhood*lr LUT: 0.1 * exp(-0.5 * sqrt(dx^2 + dy^2))
    for (int i = tid; i < 63 * 64; i += SOM_TPB) {
        float fx = (float)((i >> 6) - 31);
        float fy = (float)((i & 63) - 31);
        lut[i] = 0.1f * expf(-0.5f * sqrtf(fx * fx + fy * fy));
    }

    // register-resident state
    float w[SOM_EPW], xs[SOM_EPW], xn[SOM_EPW];
    {
        const float* wrow = W0 + (size_t)cell * SOM_DIM + lane;
#pragma unroll
        for (int k = 0; k < SOM_EPW; k++) w[k] = wrow[k * 32];
        const float* x0 = X + lane;
#pragma unroll
        for (int k = 0; k < SOM_EPW; k++) xs[k] = x0[k * 32];
        const float* x1 = X + (size_t)(1 % SOM_NS) * SOM_DIM + lane;
#pragma unroll
        for (int k = 0; k < SOM_EPW; k++) xn[k] = x1[k * 32];
    }

    // prologue: P0,Q0,R0 with w^(0); R0 == d2_0, publish it to slot row 0
    float P = 0.f, Q = 0.f, R = 0.f;
#pragma unroll
    for (int k = 0; k < SOM_EPW; k++) {
        float v = xs[k] - w[k];
        float u = xn[k] - w[k];
        R = fmaf(v, v, R);
        Q = fmaf(u, v, Q);
        P = fmaf(u, u, P);
    }
#pragma unroll
    for (int o = 16; o; o >>= 1) {
        P += __shfl_xor_sync(0xffffffffu, P, o);
        Q += __shfl_xor_sync(0xffffffffu, Q, o);
        R += __shfl_xor_sync(0xffffffffu, R, o);
    }
    if (lane == 0)
        s_cellmin[wid] =
            ((unsigned long long)__float_as_uint(R) << 32) | (unsigned)cell;
    __syncthreads();
    if (tid == 0) {
        unsigned long long m = s_cellmin[0];
#pragma unroll
        for (int j = 1; j < 8; j++) m = umin64(m, s_cellmin[j]);
        *(volatile unsigned long long*)&g_slots[cta] = m;
    }

    // ---------------- main sequential scan ----------------
    for (int s = 0; s < S; s++) {
        // prefetch x_{s+2} (hidden under the poll)
        float xf[SOM_EPW];
        {
            const int i2 = (s + 2) % SOM_NS;
            const float* xr = X + (size_t)i2 * SOM_DIM + lane;
#pragma unroll
            for (int k = 0; k < SOM_EPW; k++) xf[k] = xr[k * 32];
        }

        // warp0: poll all 128 slots of step s, reduce global min
        if (wid == 0) {
            const volatile unsigned long long* p =
                (const volatile unsigned long long*)
                    &g_slots[(size_t)s * SOM_G + (lane << 2)];
            unsigned long long a0, a1, a2, a3;
            do {
                a0 = p[0]; a1 = p[1]; a2 = p[2]; a3 = p[3];
            } while (__any_sync(0xffffffffu,
                                (a0 == INVSLOT) | (a1 == INVSLOT) |
                                (a2 == INVSLOT) | (a3 == INVSLOT)));
            unsigned long long m = umin64(umin64(a0, a1), umin64(a2, a3));
#pragma unroll
            for (int o = 16; o; o >>= 1)
                m = umin64(m, __shfl_xor_sync(0xffffffffu, m, o));
            if (lane == 0) s_bmu = m;
        }
        __syncthreads();  // bar A: BMU broadcast

        const int bcell = (int)(s_bmu & 0xffffffffull);
        const float a =
            lut[(cgx - (bcell >> 5) + 31) * 64 + (cgy - (bcell & 31) + 31)];
        const bool more = (s + 1) < S;

        // scalar combine: d2_{s+1} = P - 2aQ + a^2 R, publish ASAP
        if (more && lane == 0) {
            float d2 = fmaf(a, fmaf(a, R, -2.0f * Q), P);
            d2 = fmaxf(d2, 0.0f);
            s_cellmin[wid] =
                ((unsigned long long)__float_as_uint(d2) << 32) | (unsigned)cell;
        }
        __syncthreads();  // bar B: cell mins ready
        if (more && tid == 0) {
            unsigned long long m = s_cellmin[0];
#pragma unroll
            for (int j = 1; j < 8; j++) m = umin64(m, s_cellmin[j]);
            *(volatile unsigned long long*)&g_slots[(size_t)(s + 1) * SOM_G + cta] = m;
        }

        // hidden vector pass: update w, compute next P/Q/R
        float Pn = 0.f, Qn = 0.f, Rn = 0.f;
#pragma unroll
        for (int k = 0; k < SOM_EPW; k++) {
            float v = xs[k] - w[k];
            w[k] = fmaf(a, v, w[k]);
            float u = xn[k] - w[k];   // x_{s+1} - w^{(s+1)}  (next step's v)
            float z = xf[k] - w[k];   // x_{s+2} - w^{(s+1)}  (next step's u)
            Rn = fmaf(u, u, Rn);
            Qn = fmaf(z, u, Qn);
            Pn = fmaf(z, z, Pn);
            xs[k] = xn[k];
            xn[k] = xf[k];
        }
#pragma unroll
        for (int o = 16; o; o >>= 1) {
            Pn += __shfl_xor_sync(0xffffffffu, Pn, o);
            Qn += __shfl_xor_sync(0xffffffffu, Qn, o);
            Rn += __shfl_xor_sync(0xffffffffu, Rn, o);
        }
        P = Pn; Q = Qn; R = Rn;
    }

    // write final weights
    float* orow = out + (size_t)cell * SOM_DIM + lane;
#pragma unroll
    for (int k = 0; k < SOM_EPW; k++) orow[k * 32] = w[k];
}

extern "C" void kernel_launch(void* const* d_in, const int* in_sizes, int n_in,
                              void* d_out, int out_size) {
    const float* X  = (const float*)d_in[0];  // input_data [8192,384]
    const float* W0 = (const float*)d_in[1];  // weights    [32,32,384]
    // d_in[2] = grid_coordinates (recomputed analytically in-kernel)
    const int* pep  = (const int*)d_in[3];    // num_epochs
    (void)in_sizes; (void)n_in; (void)out_size;

    som_init_slots<<<2048, 256>>>(pep);
    som_kernel<<<SOM_G, SOM_TPB>>>(X, W0, pep, (float*)d_out);
}

// round 2
// speedup vs baseline: 2.2006x; 2.2006x over previous
#include <cuda_runtime.h>
#include <math.h>

// ---------------------------------------------------------------------------
// SOM sequential scan, persistent kernel, latency-optimized round 2.
//
// 32 CTAs x 256 threads. warp w owns 4 cells; lane holds 12 dims/cell.
// Per-step global argmin via 32 slots (one per CTA), double-buffered rows
// with a 14-bit step tag packed in the word:
//     slot = (d2_bits << 32) | (cell << 14) | ((step+1) & 0x3FFF)
// Only warp0 of each CTA touches global slots:
//     preload P,-2Q,R from smem -> poll own slot (1 per lane, relaxed.gpu)
//     -> redux.min x2 (BMU) -> LUT -> d2(step+1) -> redux.min x2 -> STG.
// No block barrier sits between poll and publish. The vector pass
// (weight update + next P/Q/R) is hidden under the following poll.
// ---------------------------------------------------------------------------

#define SOM_G      32           // CTAs == slots == lanes polling
#define SOM_TPB    256
#define SOM_DIM    384
#define SOM_NS     8192
#define SOM_EPW    12           // DIM / 32 lanes
#define SOM_CPW    4            // cells per warp
#define SOM_CPC    32           // cells per CTA
#define SOM_MAXE   2
#define TAGMASK    0x3FFFu

__device__ unsigned long long g_slots[2][SOM_G];

__device__ __forceinline__ unsigned long long ld_relaxed64(const unsigned long long* p) {
    unsigned long long v;
    asm volatile("ld.relaxed.gpu.global.b64 %0, [%1];" : "=l"(v) : "l"(p) : "memory");
    return v;
}
__device__ __forceinline__ void st_relaxed64(unsigned long long* p, unsigned long long v) {
    asm volatile("st.relaxed.gpu.global.b64 [%0], %1;" :: "l"(p), "l"(v) : "memory");
}

__device__ __forceinline__ int read_epochs(const int* p) {
    int e = p[0];
    if (e < 1 || e > SOM_MAXE) {
        float fe = __int_as_float(e);
        if (fe >= 1.0f && fe <= (float)SOM_MAXE) e = (int)fe;
        else e = 1;
    }
    return e;
}

__global__ void som_init_slots() {
    int i = threadIdx.x;
    if (i < 2 * SOM_G) ((unsigned long long*)g_slots)[i] = 0ull;
}

// warp0 helper: global (d2,cell) min over the 32 lane-held packed values.
// All packed values share the same tag, so u64 order == (d2, cell) order.
__device__ __forceinline__ unsigned long long warp_min64(unsigned long long v) {
    unsigned hi  = (unsigned)(v >> 32);
    unsigned mhi = __reduce_min_sync(0xffffffffu, hi);
    unsigned lo  = (hi == mhi) ? (unsigned)v : 0xffffffffu;
    unsigned mlo = __reduce_min_sync(0xffffffffu, lo);
    return ((unsigned long long)mhi << 32) | mlo;
}

__global__ void __launch_bounds__(SOM_TPB, 1)
som_kernel(const float* __restrict__ X,   // [8192, 384]
           const float* __restrict__ W0,  // [32, 32, 384]
           const int* __restrict__ pep,
           float* __restrict__ out)       // [32, 32, 384]
{
    __shared__ float lut[63 * 64];            // 0.1*exp(-0.5*sqrt(dx^2+dy^2))
    __shared__ float s_P[SOM_CPC], s_Qm2[SOM_CPC], s_R[SOM_CPC];
    __shared__ unsigned s_bmu;

    const int tid  = threadIdx.x;
    const int wid  = tid >> 5;
    const int lane = tid & 31;
    const int cta  = blockIdx.x;
    const int S    = read_epochs(pep) * SOM_NS;

    // cells owned by this warp: base + c, c in [0,4)
    const int cell0 = cta * SOM_CPC + wid * SOM_CPW;

    for (int i = tid; i < 63 * 64; i += SOM_TPB) {
        float fx = (float)((i >> 6) - 31);
        float fy = (float)((i & 63) - 31);
        lut[i] = 0.1f * expf(-0.5f * sqrtf(fx * fx + fy * fy));
    }

    // register state
    float w[SOM_CPW][SOM_EPW];
    float xs[SOM_EPW], xn[SOM_EPW];
#pragma unroll
    for (int c = 0; c < SOM_CPW; c++) {
        const float* wr = W0 + (size_t)(cell0 + c) * SOM_DIM + lane;
#pragma unroll
        for (int k = 0; k < SOM_EPW; k++) w[c][k] = wr[k * 32];
    }
    {
        const float* x0 = X + lane;
#pragma unroll
        for (int k = 0; k < SOM_EPW; k++) xs[k] = x0[k * 32];
        const float* x1 = X + (size_t)SOM_DIM + lane;
#pragma unroll
        for (int k = 0; k < SOM_EPW; k++) xn[k] = x1[k * 32];
    }

    // prologue: per-cell P, -2Q, R with w^(0); R == d2_0
    float P[SOM_CPW], Q[SOM_CPW], R[SOM_CPW];
#pragma unroll
    for (int c = 0; c < SOM_CPW; c++) {
        float p = 0.f, q = 0.f, r = 0.f;
#pragma unroll
        for (int k = 0; k < SOM_EPW; k++) {
            float v = xs[k] - w[c][k];
            float u = xn[k] - w[c][k];
            r = fmaf(v, v, r);
            q = fmaf(u, v, q);
            p = fmaf(u, u, p);
        }
        P[c] = p; Q[c] = q; R[c] = r;
    }
#pragma unroll
    for (int o = 16; o; o >>= 1) {
#pragma unroll
        for (int c = 0; c < SOM_CPW; c++) {
            P[c] += __shfl_xor_sync(0xffffffffu, P[c], o);
            Q[c] += __shfl_xor_sync(0xffffffffu, Q[c], o);
            R[c] += __shfl_xor_sync(0xffffffffu, R[c], o);
        }
    }
    if (lane == 0) {
#pragma unroll
        for (int c = 0; c < SOM_CPW; c++) {
            s_P[wid * SOM_CPW + c]   = P[c];
            s_Qm2[wid * SOM_CPW + c] = -2.0f * Q[c];
            s_R[wid * SOM_CPW + c]   = R[c];
        }
    }
    __syncthreads();

    // publish step-0 mins: d2_0 = R, tag 1, row 0
    if (wid == 0) {
        float d2 = s_R[lane];
        unsigned pcell = cta * SOM_CPC + lane;
        unsigned long long pk = ((unsigned long long)__float_as_uint(d2) << 32)
                              | (pcell << 14) | 1u;
        unsigned long long m = warp_min64(pk);
        if (lane == 0) st_relaxed64(&g_slots[0][cta], m);
    }
    __syncthreads();

    // ---------------- main loop ----------------
    for (int s = 0; s < S; s++) {
        // prefetch x_{s+2}
        float xf[SOM_EPW];
        {
            const float* xr = X + (size_t)((s + 2) & (SOM_NS - 1)) * SOM_DIM + lane;
#pragma unroll
            for (int k = 0; k < SOM_EPW; k++) xf[k] = xr[k * 32];
        }

        if (wid == 0) {
            // preload publish operands BEFORE the poll (off critical path)
            float Pp = s_P[lane], Qp = s_Qm2[lane], Rp = s_R[lane];
            const unsigned pcell = cta * SOM_CPC + lane;
            const int pgx = pcell >> 5, pgy = pcell & 31;

            // poll own slot
            const unsigned tag = (unsigned)(s + 1) & TAGMASK;
            unsigned long long v;
            const unsigned long long* sp = &g_slots[s & 1][lane];
            do { v = ld_relaxed64(sp); } while ((unsigned)(v & TAGMASK) != tag);

            // global BMU
            unsigned long long gm = warp_min64(v);
            unsigned bcell = ((unsigned)gm >> 14) & 0x3FFu;
            if (lane == 0) s_bmu = bcell;

            // publish step s+1 immediately
            if (s + 1 < S) {
                const int bx = bcell >> 5, by = bcell & 31;
                float a = lut[(pgx - bx + 31) * 64 + (pgy - by + 31)];
                float d2 = fmaf(a, fmaf(a, Rp, Qp), Pp);
                d2 = fmaxf(d2, 0.0f);
                unsigned long long pk =
                    ((unsigned long long)__float_as_uint(d2) << 32)
                    | (pcell << 14) | ((unsigned)(s + 2) & TAGMASK);
                unsigned long long m = warp_min64(pk);
                if (lane == 0) st_relaxed64(&g_slots[(s + 1) & 1][cta], m);
            }
        }
        __syncthreads();  // bmu visible to all warps

        const unsigned bcell = s_bmu;
        const int bx = bcell >> 5, by = bcell & 31;

        // hidden vector pass: update 4 cells, compute next P,-2Q,R
#pragma unroll
        for (int c = 0; c < SOM_CPW; c++) {
            const int cl = cell0 + c;
            const float a = lut[((cl >> 5) - bx + 31) * 64 + ((cl & 31) - by + 31)];
            float p = 0.f, q = 0.f, r = 0.f;
#pragma unroll
            for (int k = 0; k < SOM_EPW; k++) {
                float v = xs[k] - w[c][k];
                float wn = fmaf(a, v, w[c][k]);
                w[c][k] = wn;
                float u = xn[k] - wn;   // next v
                float z = xf[k] - wn;   // next u
                r = fmaf(u, u, r);
                q = fmaf(z, u, q);
                p = fmaf(z, z, p);
            }
            P[c] = p; Q[c] = q; R[c] = r;
        }
#pragma unroll
        for (int o = 16; o; o >>= 1) {
#pragma unroll
            for (int c = 0; c < SOM_CPW; c++) {
                P[c] += __shfl_xor_sync(0xffffffffu, P[c], o);
                Q[c] += __shfl_xor_sync(0xffffffffu, Q[c], o);
                R[c] += __shfl_xor_sync(0xffffffffu, R[c], o);
            }
        }
        if (lane == 0) {
#pragma unroll
            for (int c = 0; c < SOM_CPW; c++) {
                s_P[wid * SOM_CPW + c]   = P[c];
                s_Qm2[wid * SOM_CPW + c] = -2.0f * Q[c];
                s_R[wid * SOM_CPW + c]   = R[c];
            }
        }
#pragma unroll
        for (int k = 0; k < SOM_EPW; k++) { xs[k] = xn[k]; xn[k] = xf[k]; }

        __syncthreads();  // P/Q/R ready for warp0's next publish
    }

    // write final weights
#pragma unroll
    for (int c = 0; c < SOM_CPW; c++) {
        float* orow = out + (size_t)(cell0 + c) * SOM_DIM + lane;
#pragma unroll
        for (int k = 0; k < SOM_EPW; k++) orow[k * 32] = w[c][k];
    }
}

extern "C" void kernel_launch(void* const* d_in, const int* in_sizes, int n_in,
                              void* d_out, int out_size) {
    const float* X  = (const float*)d_in[0];
    const float* W0 = (const float*)d_in[1];
    const int* pep  = (const int*)d_in[3];
    (void)in_sizes; (void)n_in; (void)out_size;

    som_init_slots<<<1, 64>>>();
    som_kernel<<<SOM_G, SOM_TPB>>>(X, W0, pep, (float*)d_out);
}

// round 4
// speedup vs baseline: 3.8668x; 1.7572x over previous
#include <cuda_runtime.h>
#include <math.h>

// ---------------------------------------------------------------------------
// SOM sequential scan, round 4 (= round 3 resubmit + pre-poll operand hoist).
//
// 128 CTAs x 288 threads (9 warps). Warp 0 = comm-only. Warps 1..8 each own
// ONE cell (cell = cta*8 + wid-1), 12 dims/lane, weights in registers.
//
// Per-step global argmin: 128 slots (one per CTA), double-buffered rows,
// 14-bit step tag packed in the word:
//     slot = (d2_bits << 32) | (cell << 14) | (step+1)
// Comm warp per step:
//     bar2.wait + LDS publish operands (off critical path)
//     -> poll 4 slots/lane (relaxed.gpu) -> redux-min pair (BMU)
//     -> LUT + 2 FMA -> redux-min pair -> relaxed STG -> bar1.arrive.
// Workers: prefetch x_{s+2}; bar1.sync (get BMU); update w + next P/-2Q/R;
//     butterfly; STS; bar2.arrive. Pass (~350 cyc) hides under comm RTT.
// ---------------------------------------------------------------------------

#define SOM_G    128
#define SOM_TPB  288
#define SOM_DIM  384
#define SOM_NS   8192
#define SOM_EPW  12          // dims per lane
#define SOM_CPC  8           // cells per CTA
#define SOM_MAXE 2
#define TAGMASK  0x3FFFu

__device__ unsigned long long g_slots[2][SOM_G];

static __device__ __forceinline__ unsigned long long ld_rlx(const unsigned long long* p) {
    unsigned long long v;
    asm volatile("ld.relaxed.gpu.global.b64 %0, [%1];" : "=l"(v) : "l"(p) : "memory");
    return v;
}
static __device__ __forceinline__ void st_rlx(unsigned long long* p, unsigned long long v) {
    asm volatile("st.relaxed.gpu.global.b64 [%0], %1;" :: "l"(p), "l"(v) : "memory");
}
static __device__ __forceinline__ void bar_arrive(int id) {
    asm volatile("bar.arrive %0, %1;" :: "r"(id), "r"(SOM_TPB) : "memory");
}
static __device__ __forceinline__ void bar_wait(int id) {
    asm volatile("bar.sync %0, %1;" :: "r"(id), "r"(SOM_TPB) : "memory");
}
static __device__ __forceinline__ unsigned long long umin64(unsigned long long a,
                                                            unsigned long long b) {
    return a < b ? a : b;
}
// warp-wide min of packed (d2<<32 | cell<<14 | tag); tags identical across lanes
static __device__ __forceinline__ unsigned long long warp_min64(unsigned long long v) {
    unsigned hi  = (unsigned)(v >> 32);
    unsigned mhi = __reduce_min_sync(0xffffffffu, hi);
    unsigned lo  = (hi == mhi) ? (unsigned)v : 0xffffffffu;
    unsigned mlo = __reduce_min_sync(0xffffffffu, lo);
    return ((unsigned long long)mhi << 32) | mlo;
}

static __device__ __forceinline__ int read_epochs(const int* p) {
    int e = p[0];
    if (e < 1 || e > SOM_MAXE) {
        float fe = __int_as_float(e);
        if (fe >= 1.0f && fe <= (float)SOM_MAXE) e = (int)fe;
        else e = 1;
    }
    return e;
}

__global__ void som_init_slots() {
    int i = threadIdx.x;
    if (i < 2 * SOM_G) ((unsigned long long*)g_slots)[i] = 0ull;
}

__global__ void __launch_bounds__(SOM_TPB, 1)
som_kernel(const float* __restrict__ X,   // [8192, 384]
           const float* __restrict__ W0,  // [32, 32, 384]
           const int* __restrict__ pep,
           float* __restrict__ out)       // [32, 32, 384]
{
    __shared__ float lut[63 * 64];               // 0.1*exp(-0.5*sqrt(dx^2+dy^2))
    __shared__ float s_P[SOM_CPC], s_Qm2[SOM_CPC], s_R[SOM_CPC];
    __shared__ unsigned s_bmu[2];

    const int tid  = threadIdx.x;
    const int wid  = tid >> 5;
    const int lane = tid & 31;
    const int cta  = blockIdx.x;
    const int S    = read_epochs(pep) * SOM_NS;

    for (int i = tid; i < 63 * 64; i += SOM_TPB) {
        float fx = (float)((i >> 6) - 31);
        float fy = (float)((i & 63) - 31);
        lut[i] = 0.1f * expf(-0.5f * sqrtf(fx * fx + fy * fy));
    }

    // ---------------- worker state + prologue ----------------
    float w[SOM_EPW], v[SOM_EPW], xn[SOM_EPW];
    int cell = 0, cgx = 0, cgy = 0;
    if (wid > 0) {
        cell = cta * SOM_CPC + (wid - 1);
        cgx = cell >> 5; cgy = cell & 31;
        const float* wr = W0 + (size_t)cell * SOM_DIM + lane;
#pragma unroll
        for (int k = 0; k < SOM_EPW; k++) w[k] = wr[k * 32];
        const float* x0 = X + lane;
        const float* x1 = X + (size_t)SOM_DIM + lane;
        float p = 0.f, q = 0.f, r = 0.f;
#pragma unroll
        for (int k = 0; k < SOM_EPW; k++) {
            float a0 = x0[k * 32];
            float a1 = x1[k * 32];
            float vv = a0 - w[k];
            float uu = a1 - w[k];
            v[k]  = vv;
            xn[k] = a1;
            r = fmaf(vv, vv, r);
            q = fmaf(uu, vv, q);
            p = fmaf(uu, uu, p);
        }
#pragma unroll
        for (int o = 16; o; o >>= 1) {
            p += __shfl_xor_sync(0xffffffffu, p, o);
            q += __shfl_xor_sync(0xffffffffu, q, o);
            r += __shfl_xor_sync(0xffffffffu, r, o);
        }
        if (lane == 0) {
            s_P[wid - 1]   = p;
            s_Qm2[wid - 1] = -2.0f * q;
            s_R[wid - 1]   = r;
        }
    }
    __syncthreads();

    if (wid == 0) {
        // ================= COMM WARP =================
        // publish step-0 mins (d2_0 == R), tag 1, row 0
        {
            unsigned long long pk = 0xFFFFFFFFFFFFFFFFull;
            if (lane < SOM_CPC) {
                unsigned pcell = (unsigned)(cta * SOM_CPC + lane);
                pk = ((unsigned long long)__float_as_uint(s_R[lane]) << 32)
                   | (pcell << 14) | 1u;
            }
            unsigned long long m = warp_min64(pk);
            if (lane == 0) st_rlx(&g_slots[0][cta], m);
        }

        const unsigned pc = (unsigned)(cta * SOM_CPC + (lane & 7));
        const int pgx = (int)(pc >> 5), pgy = (int)(pc & 31);

        for (int s = 0; s < S; s++) {
            const bool more = (s + 1 < S);

            // fetch publish operands BEFORE the poll (workers produced them
            // a full round-trip ago; this wait is essentially free here)
            float Pp = 0.f, Qp = 0.f, Rp = 0.f;
            if (more) {
                bar_wait(2);
                if (lane < SOM_CPC) {
                    Pp = s_P[lane]; Qp = s_Qm2[lane]; Rp = s_R[lane];
                }
            }

            // poll own 4 slots for step s
            const unsigned tag = (unsigned)(s + 1) & TAGMASK;
            const unsigned long long* base = &g_slots[s & 1][0];
            const unsigned long long *q0 = base + lane,      *q1 = base + lane + 32,
                                     *q2 = base + lane + 64, *q3 = base + lane + 96;
            unsigned long long v0 = ld_rlx(q0), v1 = ld_rlx(q1),
                               v2 = ld_rlx(q2), v3 = ld_rlx(q3);
            for (;;) {
                bool b0 = ((unsigned)v0 & TAGMASK) != tag;
                bool b1 = ((unsigned)v1 & TAGMASK) != tag;
                bool b2 = ((unsigned)v2 & TAGMASK) != tag;
                bool b3 = ((unsigned)v3 & TAGMASK) != tag;
                if (!(b0 | b1 | b2 | b3)) break;
                if (b0) v0 = ld_rlx(q0);
                if (b1) v1 = ld_rlx(q1);
                if (b2) v2 = ld_rlx(q2);
                if (b3) v3 = ld_rlx(q3);
            }
            __syncwarp();
            unsigned long long gm =
                warp_min64(umin64(umin64(v0, v1), umin64(v2, v3)));
            const unsigned bcell = ((unsigned)gm >> 14) & 0x3FFu;
            if (lane == 0) s_bmu[s & 1] = bcell;

            // publish step s+1 immediately
            if (more) {
                unsigned long long pk = 0xFFFFFFFFFFFFFFFFull;
                if (lane < SOM_CPC) {
                    float a = lut[(pgx - (int)(bcell >> 5) + 31) * 64 +
                                  (pgy - (int)(bcell & 31) + 31)];
                    float d2 = fmaxf(fmaf(a, fmaf(a, Rp, Qp), Pp), 0.0f);
                    pk = ((unsigned long long)__float_as_uint(d2) << 32)
                       | (pc << 14) | ((unsigned)(s + 2) & TAGMASK);
                }
                unsigned long long pm = warp_min64(pk);
                if (lane == 0) st_rlx(&g_slots[(s + 1) & 1][cta], pm);
            }
            bar_arrive(1);  // release workers for step s
        }
    } else {
        // ================= WORKER WARPS =================
        if (S > 1) bar_arrive(2);  // prologue P/Q/R already in smem

        for (int s = 0; s < S; s++) {
            // prefetch x_{s+2} while waiting for BMU(s)
            float xf[SOM_EPW];
            {
                const float* xr =
                    X + (size_t)((s + 2) & (SOM_NS - 1)) * SOM_DIM + lane;
#pragma unroll
                for (int k = 0; k < SOM_EPW; k++) xf[k] = xr[k * 32];
            }
            bar_wait(1);  // BMU(s) ready
            const unsigned bcell = s_bmu[s & 1];
            const float a = lut[(cgx - (int)(bcell >> 5) + 31) * 64 +
                                (cgy - (int)(bcell & 31) + 31)];

            float p = 0.f, q = 0.f, r = 0.f;
#pragma unroll
            for (int k = 0; k < SOM_EPW; k++) {
                float wn = fmaf(a, v[k], w[k]);   // w^(s+1)
                float u  = xn[k] - wn;            // x_{s+1} - w^(s+1) = next v
                float z  = xf[k] - wn;            // x_{s+2} - w^(s+1)
                r = fmaf(u, u, r);
                q = fmaf(z, u, q);
                p = fmaf(z, z, p);
                w[k]  = wn;
                v[k]  = u;
                xn[k] = xf[k];
            }
            if (s + 2 < S) {
#pragma unroll
                for (int o = 16; o; o >>= 1) {
                    p += __shfl_xor_sync(0xffffffffu, p, o);
                    q += __shfl_xor_sync(0xffffffffu, q, o);
                    r += __shfl_xor_sync(0xffffffffu, r, o);
                }
                if (lane == 0) {
                    s_P[wid - 1]   = p;
                    s_Qm2[wid - 1] = -2.0f * q;
                    s_R[wid - 1]   = r;
                }
                bar_arrive(2);
            }
        }

        // write final weights
        float* orow = out + (size_t)cell * SOM_DIM + lane;
#pragma unroll
        for (int k = 0; k < SOM_EPW; k++) orow[k * 32] = w[k];
    }
}

extern "C" void kernel_launch(void* const* d_in, const int* in_sizes, int n_in,
                              void* d_out, int out_size) {
    const float* X  = (const float*)d_in[0];
    const float* W0 = (const float*)d_in[1];
    const int* pep  = (const int*)d_in[3];
    (void)in_sizes; (void)n_in; (void)out_size;

    som_init_slots<<<1, 256>>>();
    som_kernel<<<SOM_G, SOM_TPB>>>(X, W0, pep, (float*)d_out);
}